// round 3
// baseline (speedup 1.0000x reference)
#include <cuda_runtime.h>
#include <cstdint>

#define KQW      50
#define NCH      128          // key/value channels
#define NBINS    4096         // coarse: (positive float bits) >> 19
#define CAND_CAP 16384
#define SEL_CAP  4096
#define MAXN     1048576
#define NB_DIST  608          // 152 SMs * 4 blocks

// ---- scratch (device globals, zero at module load; kernels self-clean) ----
__device__ float    g_w[MAXN];          // per-row weights (4 MB, L2-resident)
__device__ float    g_bsum[NB_DIST];    // per-block partial sums of weights
__device__ unsigned g_hist[NBINS];      // coarse histogram (bits >> 19)
__device__ unsigned g_hist2[NBINS];     // sub-histogram of boundary bin (bits 7..18)
__device__ float    g_wsum;             // total weight sum
__device__ unsigned g_thresh_bin;       // boundary coarse bin b*
__device__ unsigned g_above;            // count strictly above b* (< 50)
__device__ unsigned g_sub_bin;          // sub-bin threshold within b*
__device__ unsigned g_ncand;            // candidate counter
__device__ int      g_cand[CAND_CAP];   // candidate row indices

__device__ __forceinline__ unsigned coarse_bin(unsigned u) { return u >> 19; }
__device__ __forceinline__ unsigned sub_bin(unsigned u)    { return (u >> 7) & 0xFFFu; }

// ------------------------------------------------------------------
// K1: the 512MB streaming pass (unchanged from R2; ~HBM roof).
// ------------------------------------------------------------------
__device__ __forceinline__ void commit4(
    float4 a0, float4 a1, float4 a2, float4 a3,
    float4 kq, int row, int nwarp, int lane,
    unsigned* hist, float& lsum)
{
    float dx, dy, dz, dw;
    dx = kq.x - a0.x; dy = kq.y - a0.y; dz = kq.z - a0.z; dw = kq.w - a0.w;
    float s0 = dx*dx + dy*dy + dz*dz + dw*dw;
    dx = kq.x - a1.x; dy = kq.y - a1.y; dz = kq.z - a1.z; dw = kq.w - a1.w;
    float s1 = dx*dx + dy*dy + dz*dz + dw*dw;
    dx = kq.x - a2.x; dy = kq.y - a2.y; dz = kq.z - a2.z; dw = kq.w - a2.w;
    float s2 = dx*dx + dy*dy + dz*dz + dw*dw;
    dx = kq.x - a3.x; dy = kq.y - a3.y; dz = kq.z - a3.z; dw = kq.w - a3.w;
    float s3 = dx*dx + dy*dy + dz*dz + dw*dw;

    #pragma unroll
    for (int o = 16; o >= 4; o >>= 1) {
        s0 += __shfl_xor_sync(0xffffffffu, s0, o);
        s1 += __shfl_xor_sync(0xffffffffu, s1, o);
        s2 += __shfl_xor_sync(0xffffffffu, s2, o);
        s3 += __shfl_xor_sync(0xffffffffu, s3, o);
    }
    const int g = lane >> 3;
    float t = s0;
    if (g == 1) t = s1;
    if (g == 2) t = s2;
    if (g == 3) t = s3;
    t += __shfl_xor_sync(0xffffffffu, t, 2);
    t += __shfl_xor_sync(0xffffffffu, t, 1);
    if ((lane & 7) == 0) {
        float wv = 1.f / (t + 1e-3f);
        g_w[row + g * nwarp] = wv;
        atomicAdd(&hist[__float_as_uint(wv) >> 19], 1u);
        lsum += wv;
    }
}

__global__ void __launch_bounds__(256, 4)
k_dist(const float* __restrict__ key, const float* __restrict__ keys, int n) {
    __shared__ unsigned hist[NBINS];
    __shared__ float    ssum[8];
    for (int i = threadIdx.x; i < NBINS; i += 256) hist[i] = 0u;
    __syncthreads();

    const int lane  = threadIdx.x & 31;
    const int wid   = threadIdx.x >> 5;
    const int gwarp = (blockIdx.x * 256 + threadIdx.x) >> 5;
    const int nwarp = (gridDim.x * 256) >> 5;
    const int step  = 4 * nwarp;

    const float4* kp = reinterpret_cast<const float4*>(keys);
    const float4  kq = reinterpret_cast<const float4*>(key)[lane];

    float lsum = 0.f;
    int row = gwarp;

    if (row + 3 * nwarp < n) {
        float4 a0 = __ldcs(&kp[(size_t)row * 32 + lane]);
        float4 a1 = __ldcs(&kp[(size_t)(row +     nwarp) * 32 + lane]);
        float4 a2 = __ldcs(&kp[(size_t)(row + 2 * nwarp) * 32 + lane]);
        float4 a3 = __ldcs(&kp[(size_t)(row + 3 * nwarp) * 32 + lane]);
        int nrow = row + step;
        while (nrow + 3 * nwarp < n) {
            float4 b0 = __ldcs(&kp[(size_t)nrow * 32 + lane]);
            float4 b1 = __ldcs(&kp[(size_t)(nrow +     nwarp) * 32 + lane]);
            float4 b2 = __ldcs(&kp[(size_t)(nrow + 2 * nwarp) * 32 + lane]);
            float4 b3 = __ldcs(&kp[(size_t)(nrow + 3 * nwarp) * 32 + lane]);
            commit4(a0, a1, a2, a3, kq, row, nwarp, lane, hist, lsum);
            a0 = b0; a1 = b1; a2 = b2; a3 = b3;
            row = nrow; nrow += step;
        }
        commit4(a0, a1, a2, a3, kq, row, nwarp, lane, hist, lsum);
        row += step;
    }
    for (; row < n; row += nwarp) {
        float4 a = __ldcs(&kp[(size_t)row * 32 + lane]);
        float dx = kq.x - a.x, dy = kq.y - a.y, dz = kq.z - a.z, dw = kq.w - a.w;
        float s0 = dx*dx + dy*dy + dz*dz + dw*dw;
        #pragma unroll
        for (int o = 16; o; o >>= 1) s0 += __shfl_xor_sync(0xffffffffu, s0, o);
        if (lane == 0) {
            float wv = 1.f / (s0 + 1e-3f);
            g_w[row] = wv;
            lsum += wv;
            atomicAdd(&hist[__float_as_uint(wv) >> 19], 1u);
        }
    }

    #pragma unroll
    for (int o = 16; o; o >>= 1) lsum += __shfl_xor_sync(0xffffffffu, lsum, o);
    if (lane == 0) ssum[wid] = lsum;
    __syncthreads();
    if (threadIdx.x == 0) {
        float t = 0.f;
        for (int i = 0; i < 8; i++) t += ssum[i];
        g_bsum[blockIdx.x] = t;
    }
    for (int i = threadIdx.x; i < NBINS; i += 256) {
        unsigned cnt = hist[i];
        if (cnt) atomicAdd(&g_hist[i], cnt);
    }
}

// ------------------------------------------------------------------
// K2 (1 block): wsum (deterministic tree) + boundary coarse bin b*
// (smallest bin with top-count >= 50) + strictly-above count.
// Also zeroes g_hist2 for the upcoming refine pass.
// ------------------------------------------------------------------
__global__ void __launch_bounds__(256)
k_thresh(int nblocks) {
    __shared__ float    ss[256];
    __shared__ unsigned csum[256];
    const int tid = threadIdx.x;

    for (int i = tid; i < NBINS; i += 256) g_hist2[i] = 0u;

    float t = 0.f;
    for (int i = tid; i < nblocks; i += 256) t += g_bsum[i];
    ss[tid] = t;

    unsigned s = 0u;
    const int base = tid * (NBINS / 256);   // 16 bins / thread
    #pragma unroll
    for (int i = 0; i < NBINS / 256; i++) s += g_hist[base + i];
    csum[tid] = s;
    __syncthreads();

    for (int o = 128; o; o >>= 1) {
        if (tid < o) ss[tid] += ss[tid + o];
        __syncthreads();
    }
    if (tid == 0) {
        g_wsum = ss[0];
        unsigned cum = 0u;
        int chunk = 255;
        for (; chunk > 0; chunk--) {
            if (cum + csum[chunk] >= (unsigned)KQW) break;
            cum += csum[chunk];
        }
        int b = chunk * (NBINS / 256) + (NBINS / 256) - 1;
        for (;; b--) {
            if (b <= chunk * (NBINS / 256)) break;
            if (cum + g_hist[b] >= (unsigned)KQW) break;
            cum += g_hist[b];
        }
        if (b < 0) b = 0;
        g_thresh_bin = (unsigned)b;
        g_above = cum;          // strictly above b*, < 50
    }
}

// ------------------------------------------------------------------
// K2b: refine pass. Scan L2-resident g_w; rows landing exactly in the
// boundary bin are histogrammed by their next 12 mantissa bits.
// Also re-zeros the coarse histogram (its last reader has run).
// ------------------------------------------------------------------
__global__ void __launch_bounds__(256)
k_refine(int n, int n4) {
    const int gid = blockIdx.x * 256 + threadIdx.x;
    if (gid < NBINS) g_hist[gid] = 0u;

    const unsigned tb = g_thresh_bin;
    const float4* w4 = reinterpret_cast<const float4*>(g_w);
    const int stride = gridDim.x * 256;
    for (int i = gid; i < n4; i += stride) {
        float4 v = w4[i];
        unsigned ux = __float_as_uint(v.x), uy = __float_as_uint(v.y);
        unsigned uz = __float_as_uint(v.z), uw = __float_as_uint(v.w);
        if (coarse_bin(ux) == tb) atomicAdd(&g_hist2[sub_bin(ux)], 1u);
        if (coarse_bin(uy) == tb) atomicAdd(&g_hist2[sub_bin(uy)], 1u);
        if (coarse_bin(uz) == tb) atomicAdd(&g_hist2[sub_bin(uz)], 1u);
        if (coarse_bin(uw) == tb) atomicAdd(&g_hist2[sub_bin(uw)], 1u);
    }
    if (gid == 0) {
        for (int i = n4 * 4; i < n; i++) {
            unsigned u = __float_as_uint(g_w[i]);
            if (coarse_bin(u) == tb) atomicAdd(&g_hist2[sub_bin(u)], 1u);
        }
    }
}

// ------------------------------------------------------------------
// K2c (1 block): sub-bin threshold within b*: smallest sb* with
// count(sub >= sb*) >= need, need = 50 - above.
// ------------------------------------------------------------------
__global__ void __launch_bounds__(256)
k_thresh2() {
    __shared__ unsigned csum[256];
    const int tid = threadIdx.x;
    unsigned s = 0u;
    const int base = tid * (NBINS / 256);
    #pragma unroll
    for (int i = 0; i < NBINS / 256; i++) s += g_hist2[base + i];
    csum[tid] = s;
    __syncthreads();
    if (tid == 0) {
        const unsigned need = (unsigned)KQW - g_above;   // 1..50
        unsigned cum = 0u;
        int chunk = 255;
        for (; chunk > 0; chunk--) {
            if (cum + csum[chunk] >= need) break;
            cum += csum[chunk];
        }
        int b = chunk * (NBINS / 256) + (NBINS / 256) - 1;
        for (;; b--) {
            if (b <= chunk * (NBINS / 256)) break;
            if (cum + g_hist2[b] >= need) break;
            cum += g_hist2[b];
        }
        g_sub_bin = (unsigned)(b < 0 ? 0 : b);
    }
}

// ------------------------------------------------------------------
// K3: compact candidates: bin > b*  OR  (bin == b* AND sub >= sb*).
// Expected nc ~ 50-100. Re-zeros g_hist2 for the next replay.
// ------------------------------------------------------------------
__global__ void __launch_bounds__(256)
k_compact(int n, int n4) {
    const int gid = blockIdx.x * 256 + threadIdx.x;
    if (gid < NBINS) g_hist2[gid] = 0u;

    const unsigned tb = g_thresh_bin;
    const unsigned sb = g_sub_bin;
    const float4* w4 = reinterpret_cast<const float4*>(g_w);
    const int stride = gridDim.x * 256;

    for (int i = gid; i < n4; i += stride) {
        float4 v = w4[i];
        unsigned u[4] = { __float_as_uint(v.x), __float_as_uint(v.y),
                          __float_as_uint(v.z), __float_as_uint(v.w) };
        #pragma unroll
        for (int c = 0; c < 4; c++) {
            unsigned cb = coarse_bin(u[c]);
            if (cb > tb || (cb == tb && sub_bin(u[c]) >= sb)) {
                unsigned p = atomicAdd(&g_ncand, 1u);
                if (p < CAND_CAP) g_cand[p] = 4 * i + c;
            }
        }
    }
    if (gid == 0) {
        for (int i = n4 * 4; i < n; i++) {
            unsigned uu = __float_as_uint(g_w[i]);
            unsigned cb = coarse_bin(uu);
            if (cb > tb || (cb == tb && sub_bin(uu) >= sb)) {
                unsigned p = atomicAdd(&g_ncand, 1u);
                if (p < CAND_CAP) g_cand[p] = i;
            }
        }
    }
}

// ------------------------------------------------------------------
// K4 (1 block): exact top-50 by rank counting (value desc, index asc —
// identical tiebreak to jax.lax.top_k) on the small candidate set,
// then two-team gather + weighted sum. Resets g_ncand.
// ------------------------------------------------------------------
__global__ void __launch_bounds__(256)
k_final(const float* __restrict__ values, float* __restrict__ out) {
    __shared__ float cw[SEL_CAP];
    __shared__ int   ci[SEL_CAP];
    __shared__ float sel_w[KQW];
    __shared__ int   sel_i[KQW];
    __shared__ float part[2 * NCH];

    int nc = (int)min(g_ncand, (unsigned)CAND_CAP);
    if (nc > SEL_CAP) nc = SEL_CAP;

    for (int i = threadIdx.x; i < nc; i += 256) {
        int idx = g_cand[i];
        ci[i] = idx;
        cw[i] = g_w[idx];
    }
    for (int i = threadIdx.x; i < KQW; i += 256) { sel_w[i] = 0.f; sel_i[i] = 0; }
    __syncthreads();
    if (threadIdx.x == 0) g_ncand = 0u;   // clean for next replay

    for (int i = threadIdx.x; i < nc; i += 256) {
        const float wi = cw[i];
        const int   ii = ci[i];
        int rank = 0;
        for (int j = 0; j < nc; j++) {
            float wj = cw[j];
            rank += (wj > wi) || (wj == wi && ci[j] < ii);
        }
        if (rank < KQW) { sel_w[rank] = wi; sel_i[rank] = ii; }
    }
    __syncthreads();

    const int ns  = nc < KQW ? nc : KQW;
    const int ch  = threadIdx.x & (NCH - 1);
    const int tm  = threadIdx.x >> 7;    // two teams over selections
    float a0 = 0.f, a1 = 0.f, a2 = 0.f, a3 = 0.f;
    int j = tm;
    for (; j + 6 < ns; j += 8) {
        a0 += sel_w[j]     * __ldg(&values[(size_t)sel_i[j]     * NCH + ch]);
        a1 += sel_w[j + 2] * __ldg(&values[(size_t)sel_i[j + 2] * NCH + ch]);
        a2 += sel_w[j + 4] * __ldg(&values[(size_t)sel_i[j + 4] * NCH + ch]);
        a3 += sel_w[j + 6] * __ldg(&values[(size_t)sel_i[j + 6] * NCH + ch]);
    }
    for (; j < ns; j += 2)
        a0 += sel_w[j] * __ldg(&values[(size_t)sel_i[j] * NCH + ch]);
    part[tm * NCH + ch] = ((a0 + a1) + (a2 + a3));
    __syncthreads();
    if (threadIdx.x < NCH)
        out[threadIdx.x] = (part[threadIdx.x] + part[NCH + threadIdx.x]) / g_wsum;
}

// ------------------------------------------------------------------
extern "C" void kernel_launch(void* const* d_in, const int* in_sizes, int n_in,
                              void* d_out, int out_size) {
    const float* key    = (const float*)d_in[0];
    const float* keys   = (const float*)d_in[1];
    const float* values = (const float*)d_in[2];
    float* out = (float*)d_out;

    const int n = in_sizes[1] / NCH;   // number of memory rows (1,000,000)

    k_dist   <<<NB_DIST, 256>>>(key, keys, n);
    k_thresh <<<1, 256>>>(NB_DIST);
    k_refine <<<1024, 256>>>(n, n / 4);
    k_thresh2<<<1, 256>>>();
    k_compact<<<1024, 256>>>(n, n / 4);
    k_final  <<<1, 256>>>(values, out);
}

// round 4
// speedup vs baseline: 1.0644x; 1.0644x over previous
#include <cuda_runtime.h>
#include <cstdint>

#define KQW      50
#define NCH      128          // key/value channels
#define NBINS    4096         // coarse: (positive float bits) >> 19
#define CAND_CAP 16384
#define SEL_CAP  4096
#define MAXN     1048576
#define NB_DIST  608          // 152 SMs * 4 blocks

// ---- scratch (device globals, zero at module load; kernels self-clean) ----
__device__ float    g_w[MAXN];          // per-row weights (4 MB, L2-resident)
__device__ float    g_bsum[NB_DIST];    // per-block partial sums of weights
__device__ unsigned g_hist[NBINS];      // coarse histogram (bits >> 19)
__device__ unsigned g_hist2[NBINS];     // sub-histogram of boundary bin (bits 7..18)
__device__ float    g_wsum;             // total weight sum
__device__ unsigned g_thresh_bin;       // boundary coarse bin b*
__device__ unsigned g_above;            // count strictly above b* (< 50)
__device__ unsigned g_sub_bin;          // sub-bin threshold within b*
__device__ unsigned g_ncand;            // candidate counter
__device__ int      g_cand[CAND_CAP];   // candidate row indices

__device__ __forceinline__ unsigned coarse_bin(unsigned u) { return u >> 19; }
__device__ __forceinline__ unsigned sub_bin(unsigned u)    { return (u >> 7) & 0xFFFu; }

// ------------------------------------------------------------------
// Parallel boundary-bin search over a 4096-bin histogram in smem.
// Finds smallest bin b* with suffix-count >= need; returns via refs.
// h[]: histogram in shared. Uses csum/suf scratch (256 each).
// ------------------------------------------------------------------
__device__ __forceinline__ void find_boundary(
    const unsigned* __restrict__ h, unsigned need,
    unsigned* csum, unsigned* suf,
    unsigned* out_bin, unsigned* out_above)
{
    const int tid = threadIdx.x;
    // per-chunk sums (16 bins each)
    unsigned s = 0u;
    const int base = tid * (NBINS / 256);
    #pragma unroll
    for (int i = 0; i < NBINS / 256; i++) s += h[base + i];
    csum[tid] = s;
    suf[tid]  = s;
    __syncthreads();
    // inclusive suffix scan over chunks (Hillis-Steele)
    #pragma unroll
    for (int o = 1; o < 256; o <<= 1) {
        unsigned v = suf[tid];
        unsigned add = (tid + o < 256) ? suf[tid + o] : 0u;
        __syncthreads();
        suf[tid] = v + add;
        __syncthreads();
    }
    // exactly one chunk satisfies: strictly-above < need <= inclusive
    unsigned above_chunks = (tid + 1 < 256) ? suf[tid + 1] : 0u;
    if (above_chunks < need && suf[tid] >= need) {
        unsigned cum = above_chunks;
        int b = base + (NBINS / 256) - 1;
        for (;; b--) {
            if (b <= base) break;
            if (cum + h[b] >= need) break;
            cum += h[b];
        }
        *out_bin = (unsigned)b;
        *out_above = cum;
    }
}

// ------------------------------------------------------------------
// K1: the 512MB streaming pass (unchanged; ~HBM roof).
// ------------------------------------------------------------------
__device__ __forceinline__ void commit4(
    float4 a0, float4 a1, float4 a2, float4 a3,
    float4 kq, int row, int nwarp, int lane,
    unsigned* hist, float& lsum)
{
    float dx, dy, dz, dw;
    dx = kq.x - a0.x; dy = kq.y - a0.y; dz = kq.z - a0.z; dw = kq.w - a0.w;
    float s0 = dx*dx + dy*dy + dz*dz + dw*dw;
    dx = kq.x - a1.x; dy = kq.y - a1.y; dz = kq.z - a1.z; dw = kq.w - a1.w;
    float s1 = dx*dx + dy*dy + dz*dz + dw*dw;
    dx = kq.x - a2.x; dy = kq.y - a2.y; dz = kq.z - a2.z; dw = kq.w - a2.w;
    float s2 = dx*dx + dy*dy + dz*dz + dw*dw;
    dx = kq.x - a3.x; dy = kq.y - a3.y; dz = kq.z - a3.z; dw = kq.w - a3.w;
    float s3 = dx*dx + dy*dy + dz*dz + dw*dw;

    #pragma unroll
    for (int o = 16; o >= 4; o >>= 1) {
        s0 += __shfl_xor_sync(0xffffffffu, s0, o);
        s1 += __shfl_xor_sync(0xffffffffu, s1, o);
        s2 += __shfl_xor_sync(0xffffffffu, s2, o);
        s3 += __shfl_xor_sync(0xffffffffu, s3, o);
    }
    const int g = lane >> 3;
    float t = s0;
    if (g == 1) t = s1;
    if (g == 2) t = s2;
    if (g == 3) t = s3;
    t += __shfl_xor_sync(0xffffffffu, t, 2);
    t += __shfl_xor_sync(0xffffffffu, t, 1);
    if ((lane & 7) == 0) {
        float wv = 1.f / (t + 1e-3f);
        g_w[row + g * nwarp] = wv;
        atomicAdd(&hist[__float_as_uint(wv) >> 19], 1u);
        lsum += wv;
    }
}

__global__ void __launch_bounds__(256, 4)
k_dist(const float* __restrict__ key, const float* __restrict__ keys, int n) {
    __shared__ unsigned hist[NBINS];
    __shared__ float    ssum[8];
    for (int i = threadIdx.x; i < NBINS; i += 256) hist[i] = 0u;
    __syncthreads();

    const int lane  = threadIdx.x & 31;
    const int wid   = threadIdx.x >> 5;
    const int gwarp = (blockIdx.x * 256 + threadIdx.x) >> 5;
    const int nwarp = (gridDim.x * 256) >> 5;
    const int step  = 4 * nwarp;

    const float4* kp = reinterpret_cast<const float4*>(keys);
    const float4  kq = reinterpret_cast<const float4*>(key)[lane];

    float lsum = 0.f;
    int row = gwarp;

    if (row + 3 * nwarp < n) {
        float4 a0 = __ldcs(&kp[(size_t)row * 32 + lane]);
        float4 a1 = __ldcs(&kp[(size_t)(row +     nwarp) * 32 + lane]);
        float4 a2 = __ldcs(&kp[(size_t)(row + 2 * nwarp) * 32 + lane]);
        float4 a3 = __ldcs(&kp[(size_t)(row + 3 * nwarp) * 32 + lane]);
        int nrow = row + step;
        while (nrow + 3 * nwarp < n) {
            float4 b0 = __ldcs(&kp[(size_t)nrow * 32 + lane]);
            float4 b1 = __ldcs(&kp[(size_t)(nrow +     nwarp) * 32 + lane]);
            float4 b2 = __ldcs(&kp[(size_t)(nrow + 2 * nwarp) * 32 + lane]);
            float4 b3 = __ldcs(&kp[(size_t)(nrow + 3 * nwarp) * 32 + lane]);
            commit4(a0, a1, a2, a3, kq, row, nwarp, lane, hist, lsum);
            a0 = b0; a1 = b1; a2 = b2; a3 = b3;
            row = nrow; nrow += step;
        }
        commit4(a0, a1, a2, a3, kq, row, nwarp, lane, hist, lsum);
        row += step;
    }
    for (; row < n; row += nwarp) {
        float4 a = __ldcs(&kp[(size_t)row * 32 + lane]);
        float dx = kq.x - a.x, dy = kq.y - a.y, dz = kq.z - a.z, dw = kq.w - a.w;
        float s0 = dx*dx + dy*dy + dz*dz + dw*dw;
        #pragma unroll
        for (int o = 16; o; o >>= 1) s0 += __shfl_xor_sync(0xffffffffu, s0, o);
        if (lane == 0) {
            float wv = 1.f / (s0 + 1e-3f);
            g_w[row] = wv;
            lsum += wv;
            atomicAdd(&hist[__float_as_uint(wv) >> 19], 1u);
        }
    }

    #pragma unroll
    for (int o = 16; o; o >>= 1) lsum += __shfl_xor_sync(0xffffffffu, lsum, o);
    if (lane == 0) ssum[wid] = lsum;
    __syncthreads();
    if (threadIdx.x == 0) {
        float t = 0.f;
        for (int i = 0; i < 8; i++) t += ssum[i];
        g_bsum[blockIdx.x] = t;
    }
    for (int i = threadIdx.x; i < NBINS; i += 256) {
        unsigned cnt = hist[i];
        if (cnt) atomicAdd(&g_hist[i], cnt);
    }
}

// ------------------------------------------------------------------
// K2 (1 block): wsum (parallel tree) + boundary coarse bin b* via
// smem-staged histogram + parallel suffix scan. Zeroes g_hist2.
// ------------------------------------------------------------------
__global__ void __launch_bounds__(256)
k_thresh(int nblocks) {
    __shared__ unsigned h[NBINS];
    __shared__ unsigned csum[256];
    __shared__ unsigned suf[256];
    __shared__ float    ss[256];
    const int tid = threadIdx.x;

    // stage histogram (vectorized) + zero g_hist2
    const uint4* gh4 = reinterpret_cast<const uint4*>(g_hist);
    uint4* sh4 = reinterpret_cast<uint4*>(h);
    for (int i = tid; i < NBINS / 4; i += 256) sh4[i] = gh4[i];
    for (int i = tid; i < NBINS; i += 256) g_hist2[i] = 0u;

    float t = 0.f;
    for (int i = tid; i < nblocks; i += 256) t += g_bsum[i];
    ss[tid] = t;
    __syncthreads();
    for (int o = 128; o; o >>= 1) {
        if (tid < o) ss[tid] += ss[tid + o];
        __syncthreads();
    }
    if (tid == 0) g_wsum = ss[0];

    find_boundary(h, (unsigned)KQW, csum, suf, &g_thresh_bin, &g_above);
}

// ------------------------------------------------------------------
// K2b: refine pass over L2-resident g_w: rows in the boundary bin are
// histogrammed by bits 7..18. Also re-zeros the coarse histogram.
// ------------------------------------------------------------------
__global__ void __launch_bounds__(256)
k_refine(int n, int n4) {
    const int gid = blockIdx.x * 256 + threadIdx.x;
    if (gid < NBINS) g_hist[gid] = 0u;

    const unsigned tb = g_thresh_bin;
    const float4* w4 = reinterpret_cast<const float4*>(g_w);
    const int stride = gridDim.x * 256;
    for (int i = gid; i < n4; i += stride) {
        float4 v = w4[i];
        unsigned ux = __float_as_uint(v.x), uy = __float_as_uint(v.y);
        unsigned uz = __float_as_uint(v.z), uw = __float_as_uint(v.w);
        if (coarse_bin(ux) == tb) atomicAdd(&g_hist2[sub_bin(ux)], 1u);
        if (coarse_bin(uy) == tb) atomicAdd(&g_hist2[sub_bin(uy)], 1u);
        if (coarse_bin(uz) == tb) atomicAdd(&g_hist2[sub_bin(uz)], 1u);
        if (coarse_bin(uw) == tb) atomicAdd(&g_hist2[sub_bin(uw)], 1u);
    }
    if (gid == 0) {
        for (int i = n4 * 4; i < n; i++) {
            unsigned u = __float_as_uint(g_w[i]);
            if (coarse_bin(u) == tb) atomicAdd(&g_hist2[sub_bin(u)], 1u);
        }
    }
}

// ------------------------------------------------------------------
// K2c (1 block): sub-bin threshold within b* (parallel search).
// ------------------------------------------------------------------
__global__ void __launch_bounds__(256)
k_thresh2() {
    __shared__ unsigned h[NBINS];
    __shared__ unsigned csum[256];
    __shared__ unsigned suf[256];
    const int tid = threadIdx.x;

    const uint4* gh4 = reinterpret_cast<const uint4*>(g_hist2);
    uint4* sh4 = reinterpret_cast<uint4*>(h);
    for (int i = tid; i < NBINS / 4; i += 256) sh4[i] = gh4[i];
    __syncthreads();

    unsigned need = (unsigned)KQW - g_above;   // 1..50
    unsigned dummy_above;
    __shared__ unsigned sbin;
    find_boundary(h, need, csum, suf, &sbin, &dummy_above);
    __syncthreads();
    if (tid == 0) g_sub_bin = sbin;
}

// ------------------------------------------------------------------
// K3: compact candidates: bin > b*  OR  (bin == b* AND sub >= sb*).
// Expected nc ~ 50-100. Re-zeros g_hist2 for the next replay.
// ------------------------------------------------------------------
__global__ void __launch_bounds__(256)
k_compact(int n, int n4) {
    const int gid = blockIdx.x * 256 + threadIdx.x;
    if (gid < NBINS) g_hist2[gid] = 0u;

    const unsigned tb = g_thresh_bin;
    const unsigned sb = g_sub_bin;
    const float4* w4 = reinterpret_cast<const float4*>(g_w);
    const int stride = gridDim.x * 256;

    for (int i = gid; i < n4; i += stride) {
        float4 v = w4[i];
        unsigned u[4] = { __float_as_uint(v.x), __float_as_uint(v.y),
                          __float_as_uint(v.z), __float_as_uint(v.w) };
        #pragma unroll
        for (int c = 0; c < 4; c++) {
            unsigned cb = coarse_bin(u[c]);
            if (cb > tb || (cb == tb && sub_bin(u[c]) >= sb)) {
                unsigned p = atomicAdd(&g_ncand, 1u);
                if (p < CAND_CAP) g_cand[p] = 4 * i + c;
            }
        }
    }
    if (gid == 0) {
        for (int i = n4 * 4; i < n; i++) {
            unsigned uu = __float_as_uint(g_w[i]);
            unsigned cb = coarse_bin(uu);
            if (cb > tb || (cb == tb && sub_bin(uu) >= sb)) {
                unsigned p = atomicAdd(&g_ncand, 1u);
                if (p < CAND_CAP) g_cand[p] = i;
            }
        }
    }
}

// ------------------------------------------------------------------
// K4 (1 block): exact top-50 by rank counting (value desc, index asc —
// identical tiebreak to jax.lax.top_k) on the small candidate set,
// then two-team gather + weighted sum. Resets g_ncand.
// ------------------------------------------------------------------
__global__ void __launch_bounds__(256)
k_final(const float* __restrict__ values, float* __restrict__ out) {
    __shared__ float cw[SEL_CAP];
    __shared__ int   ci[SEL_CAP];
    __shared__ float sel_w[KQW];
    __shared__ int   sel_i[KQW];
    __shared__ float part[2 * NCH];

    int nc = (int)min(g_ncand, (unsigned)CAND_CAP);
    if (nc > SEL_CAP) nc = SEL_CAP;

    for (int i = threadIdx.x; i < nc; i += 256) {
        int idx = g_cand[i];
        ci[i] = idx;
        cw[i] = g_w[idx];
    }
    for (int i = threadIdx.x; i < KQW; i += 256) { sel_w[i] = 0.f; sel_i[i] = 0; }
    __syncthreads();
    if (threadIdx.x == 0) g_ncand = 0u;   // clean for next replay

    for (int i = threadIdx.x; i < nc; i += 256) {
        const float wi = cw[i];
        const int   ii = ci[i];
        int rank = 0;
        for (int j = 0; j < nc; j++) {
            float wj = cw[j];
            rank += (wj > wi) || (wj == wi && ci[j] < ii);
        }
        if (rank < KQW) { sel_w[rank] = wi; sel_i[rank] = ii; }
    }
    __syncthreads();

    const int ns  = nc < KQW ? nc : KQW;
    const int ch  = threadIdx.x & (NCH - 1);
    const int tm  = threadIdx.x >> 7;    // two teams over selections
    float a0 = 0.f, a1 = 0.f, a2 = 0.f, a3 = 0.f;
    int j = tm;
    for (; j + 6 < ns; j += 8) {
        a0 += sel_w[j]     * __ldg(&values[(size_t)sel_i[j]     * NCH + ch]);
        a1 += sel_w[j + 2] * __ldg(&values[(size_t)sel_i[j + 2] * NCH + ch]);
        a2 += sel_w[j + 4] * __ldg(&values[(size_t)sel_i[j + 4] * NCH + ch]);
        a3 += sel_w[j + 6] * __ldg(&values[(size_t)sel_i[j + 6] * NCH + ch]);
    }
    for (; j < ns; j += 2)
        a0 += sel_w[j] * __ldg(&values[(size_t)sel_i[j] * NCH + ch]);
    part[tm * NCH + ch] = ((a0 + a1) + (a2 + a3));
    __syncthreads();
    if (threadIdx.x < NCH)
        out[threadIdx.x] = (part[threadIdx.x] + part[NCH + threadIdx.x]) / g_wsum;
}

// ------------------------------------------------------------------
extern "C" void kernel_launch(void* const* d_in, const int* in_sizes, int n_in,
                              void* d_out, int out_size) {
    const float* key    = (const float*)d_in[0];
    const float* keys   = (const float*)d_in[1];
    const float* values = (const float*)d_in[2];
    float* out = (float*)d_out;

    const int n = in_sizes[1] / NCH;   // number of memory rows (1,000,000)

    k_dist   <<<NB_DIST, 256>>>(key, keys, n);
    k_thresh <<<1, 256>>>(NB_DIST);
    k_refine <<<1024, 256>>>(n, n / 4);
    k_thresh2<<<1, 256>>>();
    k_compact<<<1024, 256>>>(n, n / 4);
    k_final  <<<1, 256>>>(values, out);
}